// round 9
// baseline (speedup 1.0000x reference)
#include <cuda_runtime.h>
#include <math.h>

#define TPB 96
#define ROWS 192            // rows per CTA = 2 * TPB
#define RQS_BOUND 5.0f
#define NEG_HALF_LOG_2PI (-0.9189385332046727f)

typedef unsigned long long u64;

// ---- shared memory layout (float offsets) ----
#define OW1   0      // enc_W1 22x64
#define OB1   1408
#define OG1   1472
#define OBB1  1536
#define OW2   1600   // enc_W2 64x64
#define OB2   5696
#define OG2   5760
#define OBB2  5824
#define OW3   5888   // enc_W3 64x32
#define OB3   7936   // 32
// flow phase overlays the same region
#define FW1   0      // 33x64 = 2112
#define FB1   2112   // 64
#define FW2   2176   // 64x64 = 4096
#define FB2   6272   // 64
#define FW3   6336   // 64x24 (padded from 23) = 1536
#define FB3   7872   // 23 (+1 pad)
#define CTXOFF  8064             // 33 * ROWS
#define WORKOFF (8064 + 33*ROWS) // 64 * ROWS
#define SMEM_FLOATS (WORKOFF + 64*ROWS)

__device__ double g_partial[16384];
__device__ unsigned int g_done;   // zero-init; last CTA resets each launch

// ---- packed f32x2 helpers (sm_103a FFMA2, PTX-only) ----
static __device__ __forceinline__ u64 pack2(float lo, float hi) {
    u64 r; asm("mov.b64 %0, {%1, %2};" : "=l"(r) : "f"(lo), "f"(hi)); return r;
}
static __device__ __forceinline__ float lo2(u64 v) { return __uint_as_float((unsigned)v); }
static __device__ __forceinline__ float hi2(u64 v) { return __uint_as_float((unsigned)(v >> 32)); }
static __device__ __forceinline__ void ffma2(u64& d, u64 a, u64 b) {
    asm("fma.rn.f32x2 %0, %1, %2, %3;" : "=l"(d) : "l"(a), "l"(b), "l"(d));
}
static __device__ __forceinline__ u64 add2(u64 a, u64 b) {
    u64 r; asm("add.rn.f32x2 %0, %1, %2;" : "=l"(r) : "l"(a), "l"(b)); return r;
}

static __device__ __forceinline__ float softplusf(float x) {
    return fmaxf(x, 0.0f) + __logf(1.0f + __expf(-fabsf(x)));
}
static __device__ __forceinline__ float gelu_exact(float x) {
    return x * normcdff(x);
}

// 2-row packed GEMM: NIN inputs -> 64 outputs each in accA[32], accB[32]
#define GEMM64R2(NIN, WOFF, BOFF, SRCOFF)                                     \
    do {                                                                      \
        const u64* bp = reinterpret_cast<const u64*>(&smem[(BOFF)]);          \
        _Pragma("unroll")                                                     \
        for (int j = 0; j < 32; j++) { accA[j] = bp[j]; accB[j] = bp[j]; }    \
        _Pragma("unroll 2")                                                   \
        for (int i = 0; i < (NIN); i++) {                                     \
            float xa = smem[(SRCOFF) + i * ROWS + tid];                       \
            float xb = smem[(SRCOFF) + i * ROWS + tid + TPB];                 \
            u64 xa2 = pack2(xa, xa);                                          \
            u64 xb2 = pack2(xb, xb);                                          \
            const ulonglong2* wr =                                            \
                reinterpret_cast<const ulonglong2*>(&smem[(WOFF) + i * 64]);  \
            _Pragma("unroll")                                                 \
            for (int j = 0; j < 16; j++) {                                    \
                ulonglong2 w = wr[j];                                         \
                ffma2(accA[2 * j],     xa2, w.x);                             \
                ffma2(accA[2 * j + 1], xa2, w.y);                             \
                ffma2(accB[2 * j],     xb2, w.x);                             \
                ffma2(accB[2 * j + 1], xb2, w.y);                             \
            }                                                                 \
        }                                                                     \
    } while (0)

// LayerNorm + exact GELU for one 64-wide packed accumulator; store to columns
static __device__ __forceinline__ void ln_gelu_store(
    float* smem, u64* acc2, int go, int bo, int col)
{
    u64 s = acc2[0];
#pragma unroll
    for (int j = 1; j < 32; j++) s = add2(s, acc2[j]);
    float mu = (lo2(s) + hi2(s)) * (1.0f / 64.0f);
    float var = 0.0f;
#pragma unroll
    for (int j = 0; j < 32; j++) {
        float c0 = lo2(acc2[j]) - mu, c1 = hi2(acc2[j]) - mu;
        var += c0 * c0 + c1 * c1;
    }
    var *= (1.0f / 64.0f);
    float inv = rsqrtf(var + 1e-5f);
#pragma unroll
    for (int j = 0; j < 32; j++) {
        float v0 = (lo2(acc2[j]) - mu) * inv * smem[go + 2*j]     + smem[bo + 2*j];
        float v1 = (hi2(acc2[j]) - mu) * inv * smem[go + 2*j + 1] + smem[bo + 2*j + 1];
        smem[WORKOFF + (2*j) * ROWS + col]     = gelu_exact(v0);
        smem[WORKOFF + (2*j + 1) * ROWS + col] = gelu_exact(v1);
    }
}

// rational-quadratic spline step for one row
static __device__ __forceinline__ void rqs_step(const float* s3, float& z, float& ladj)
{
    float w8[8], h8[8];
#pragma unroll
    for (int m = 0; m < 8; m++) { w8[m] = s3[m]; h8[m] = s3[8 + m]; }

    float mw = w8[0], mh = h8[0];
#pragma unroll
    for (int m = 1; m < 8; m++) { mw = fmaxf(mw, w8[m]); mh = fmaxf(mh, h8[m]); }
    float sw = 0.0f, sh = 0.0f;
#pragma unroll
    for (int m = 0; m < 8; m++) {
        w8[m] = __expf(w8[m] - mw); sw += w8[m];
        h8[m] = __expf(h8[m] - mh); sh += h8[m];
    }
    float scw = __fdividef(2.0f * RQS_BOUND, sw);
    float sch = __fdividef(2.0f * RQS_BOUND, sh);

    float xs[9], ys[9], ds[9];
    xs[0] = -RQS_BOUND; ys[0] = -RQS_BOUND;
    float cw = 0.0f, ch = 0.0f;
#pragma unroll
    for (int m = 0; m < 8; m++) {
        cw += w8[m] * scw; xs[m + 1] = -RQS_BOUND + cw;
        ch += h8[m] * sch; ys[m + 1] = -RQS_BOUND + ch;
    }
    ds[0] = 1.0f; ds[8] = 1.0f;
#pragma unroll
    for (int m = 0; m < 7; m++) ds[m + 1] = softplusf(s3[16 + m]);

    bool inside = (z > -RQS_BOUND) && (z < RQS_BOUND);
    float xc = fminf(fmaxf(z, -RQS_BOUND), RQS_BOUND);

    int k = -1;
#pragma unroll
    for (int m = 0; m < 8; m++) k += (xc >= xs[m]) ? 1 : 0;
    k = min(max(k, 0), 7);

    float x0 = xs[0], x1 = xs[1], y0 = ys[0], y1 = ys[1], d0 = ds[0], d1 = ds[1];
#pragma unroll
    for (int m = 1; m < 8; m++) {
        if (k == m) { x0 = xs[m]; x1 = xs[m + 1]; y0 = ys[m]; y1 = ys[m + 1]; d0 = ds[m]; d1 = ds[m + 1]; }
    }

    float wk = x1 - x0, hk = y1 - y0;
    float sk = __fdividef(hk, wk);
    float xi = __fdividef(xc - x0, wk);
    float om = 1.0f - xi;
    float den = sk + (d0 + d1 - 2.0f * sk) * xi * om;
    float yin = y0 + hk * __fdividef(sk * xi * xi + d0 * xi * om, den);
    float ldin = 2.0f * (__logf(sk) - __logf(den))
               + __logf(d1 * xi * xi + 2.0f * sk * xi * om + d0 * om * om);
    if (inside) { z = yin; ladj += ldin; }
}

__global__ __launch_bounds__(TPB, 2)
void fused_kernel(
    const float* __restrict__ metadata, const float* __restrict__ prot,
    const float* __restrict__ age,      const float* __restrict__ maskp,
    const float* __restrict__ eW1, const float* __restrict__ eb1,
    const float* __restrict__ eg1, const float* __restrict__ eB1,
    const float* __restrict__ eW2, const float* __restrict__ eb2,
    const float* __restrict__ eg2, const float* __restrict__ eB2,
    const float* __restrict__ eW3, const float* __restrict__ eb3,
    const float* __restrict__ fW1, const float* __restrict__ fb1,
    const float* __restrict__ fW2, const float* __restrict__ fb2,
    const float* __restrict__ fW3, const float* __restrict__ fb3,
    float* __restrict__ out_latent, float* __restrict__ out_logprob,
    float* __restrict__ out_nll, int B, int T, int nb, float invB)
{
    extern __shared__ __align__(16) float smem[];
    __shared__ int s_islast;
    const int tid = threadIdx.x;
    const long long rowA = (long long)blockIdx.x * ROWS + tid;
    const long long rowB = rowA + TPB;
    const bool validA = (rowA < (long long)B);
    const bool validB = (rowB < (long long)B);
    const long long ra = validA ? rowA : 0;
    const long long rb = validB ? rowB : 0;

    // ---- stage encoder weights ----
    for (int i = tid; i < 1408; i += TPB) smem[OW1 + i] = eW1[i];
    for (int i = tid; i < 4096; i += TPB) smem[OW2 + i] = eW2[i];
    for (int i = tid; i < 2048; i += TPB) smem[OW3 + i] = eW3[i];
    if (tid < 64) {
        smem[OB1 + tid] = eb1[tid]; smem[OG1 + tid] = eg1[tid]; smem[OBB1 + tid] = eB1[tid];
        smem[OB2 + tid] = eb2[tid]; smem[OG2 + tid] = eg2[tid]; smem[OBB2 + tid] = eB2[tid];
    }
    if (tid < 32) smem[OB3 + tid] = eb3[tid];

    // ---- stage inputs into per-thread work columns ----
#pragma unroll
    for (int i = 0; i < 11; i++) {
        smem[WORKOFF + i * ROWS + tid]              = metadata[ra * 11 + i];
        smem[WORKOFF + i * ROWS + tid + TPB]        = metadata[rb * 11 + i];
        smem[WORKOFF + (11 + i) * ROWS + tid]       = maskp[ra * 11 + i];
        smem[WORKOFF + (11 + i) * ROWS + tid + TPB] = maskp[rb * 11 + i];
    }
    __syncthreads();

    u64 accA[32], accB[32];

    // ---- GEMM1: 22 -> 64, LN + GELU ----
    GEMM64R2(22, OW1, OB1, WORKOFF);
    ln_gelu_store(smem, accA, OG1, OBB1, tid);
    ln_gelu_store(smem, accB, OG1, OBB1, tid + TPB);

    // ---- GEMM2: 64 -> 64, LN + GELU ----
    GEMM64R2(64, OW2, OB2, WORKOFF);
    ln_gelu_store(smem, accA, OG2, OBB2, tid);
    ln_gelu_store(smem, accB, OG2, OBB2, tid + TPB);

    // ---- GEMM3: 64 -> 32 (latent) ----
    {
        u64 latA[16], latB[16];
        const u64* bp = reinterpret_cast<const u64*>(&smem[OB3]);
#pragma unroll
        for (int j = 0; j < 16; j++) { latA[j] = bp[j]; latB[j] = bp[j]; }
#pragma unroll 2
        for (int i = 0; i < 64; i++) {
            float xa = smem[WORKOFF + i * ROWS + tid];
            float xb = smem[WORKOFF + i * ROWS + tid + TPB];
            u64 xa2 = pack2(xa, xa);
            u64 xb2 = pack2(xb, xb);
            const ulonglong2* wr = reinterpret_cast<const ulonglong2*>(&smem[OW3 + i * 32]);
#pragma unroll
            for (int j = 0; j < 8; j++) {
                ulonglong2 w = wr[j];
                ffma2(latA[2 * j],     xa2, w.x);
                ffma2(latA[2 * j + 1], xa2, w.y);
                ffma2(latB[2 * j],     xb2, w.x);
                ffma2(latB[2 * j + 1], xb2, w.y);
            }
        }
        if (validA) {
            float4* lp4 = reinterpret_cast<float4*>(out_latent + rowA * 32);
#pragma unroll
            for (int q = 0; q < 8; q++)
                lp4[q] = make_float4(lo2(latA[2 * q]), hi2(latA[2 * q]),
                                     lo2(latA[2 * q + 1]), hi2(latA[2 * q + 1]));
        }
        if (validB) {
            float4* lp4 = reinterpret_cast<float4*>(out_latent + rowB * 32);
#pragma unroll
            for (int q = 0; q < 8; q++)
                lp4[q] = make_float4(lo2(latB[2 * q]), hi2(latB[2 * q]),
                                     lo2(latB[2 * q + 1]), hi2(latB[2 * q + 1]));
        }
#pragma unroll
        for (int j = 0; j < 16; j++) {
            smem[CTXOFF + (2 * j) * ROWS + tid]           = lo2(latA[j]);
            smem[CTXOFF + (2 * j + 1) * ROWS + tid]       = hi2(latA[j]);
            smem[CTXOFF + (2 * j) * ROWS + tid + TPB]     = lo2(latB[j]);
            smem[CTXOFF + (2 * j + 1) * ROWS + tid + TPB] = hi2(latB[j]);
        }
        smem[CTXOFF + 32 * ROWS + tid]       = prot[ra];
        smem[CTXOFF + 32 * ROWS + tid + TPB] = prot[rb];
    }

    // ---- flow transforms ----
    float zA = age[ra], zB = age[rb];
    float ladjA = 0.0f, ladjB = 0.0f;

    for (int t = 0; t < T; t++) {
        __syncthreads();
        const float* w1t = fW1 + (long long)t * 2112;
        const float* w2t = fW2 + (long long)t * 4096;
        const float* w3t = fW3 + (long long)t * 1472;
        for (int i = tid; i < 2112; i += TPB) smem[FW1 + i] = w1t[i];
        for (int i = tid; i < 4096; i += TPB) smem[FW2 + i] = w2t[i];
        for (int i = tid; i < 1472; i += TPB) {
            int rr = i / 23, cc = i - rr * 23;
            smem[FW3 + rr * 24 + cc] = w3t[i];
        }
        if (tid < 64) {
            smem[FB1 + tid] = fb1[t * 64 + tid];
            smem[FB2 + tid] = fb2[t * 64 + tid];
            smem[FW3 + tid * 24 + 23] = 0.0f;
        }
        if (tid < 24) smem[FB3 + tid] = (tid < 23) ? fb3[t * 23 + tid] : 0.0f;
        __syncthreads();

        // p1 = relu(ctx @ W1 + b1)
        GEMM64R2(33, FW1, FB1, CTXOFF);
#pragma unroll
        for (int j = 0; j < 32; j++) {
            smem[WORKOFF + (2 * j) * ROWS + tid]           = fmaxf(lo2(accA[j]), 0.0f);
            smem[WORKOFF + (2 * j + 1) * ROWS + tid]       = fmaxf(hi2(accA[j]), 0.0f);
            smem[WORKOFF + (2 * j) * ROWS + tid + TPB]     = fmaxf(lo2(accB[j]), 0.0f);
            smem[WORKOFF + (2 * j + 1) * ROWS + tid + TPB] = fmaxf(hi2(accB[j]), 0.0f);
        }

        // p2 = relu(p1 @ W2 + b2)
        GEMM64R2(64, FW2, FB2, WORKOFF);
#pragma unroll
        for (int j = 0; j < 32; j++) {
            smem[WORKOFF + (2 * j) * ROWS + tid]           = fmaxf(lo2(accA[j]), 0.0f);
            smem[WORKOFF + (2 * j + 1) * ROWS + tid]       = fmaxf(hi2(accA[j]), 0.0f);
            smem[WORKOFF + (2 * j) * ROWS + tid + TPB]     = fmaxf(lo2(accB[j]), 0.0f);
            smem[WORKOFF + (2 * j + 1) * ROWS + tid + TPB] = fmaxf(hi2(accB[j]), 0.0f);
        }

        // p3 = p2 @ W3 + b3   (23 outputs, padded to 24)
        float s3A[24], s3B[24];
        {
            u64 sA[12], sB[12];
            const u64* bp = reinterpret_cast<const u64*>(&smem[FB3]);
#pragma unroll
            for (int j = 0; j < 12; j++) { sA[j] = bp[j]; sB[j] = bp[j]; }
#pragma unroll 2
            for (int i = 0; i < 64; i++) {
                float xa = smem[WORKOFF + i * ROWS + tid];
                float xb = smem[WORKOFF + i * ROWS + tid + TPB];
                u64 xa2 = pack2(xa, xa);
                u64 xb2 = pack2(xb, xb);
                const ulonglong2* wr = reinterpret_cast<const ulonglong2*>(&smem[FW3 + i * 24]);
#pragma unroll
                for (int j = 0; j < 6; j++) {
                    ulonglong2 w = wr[j];
                    ffma2(sA[2 * j],     xa2, w.x);
                    ffma2(sA[2 * j + 1], xa2, w.y);
                    ffma2(sB[2 * j],     xb2, w.x);
                    ffma2(sB[2 * j + 1], xb2, w.y);
                }
            }
#pragma unroll
            for (int j = 0; j < 12; j++) {
                s3A[2 * j] = lo2(sA[j]); s3A[2 * j + 1] = hi2(sA[j]);
                s3B[2 * j] = lo2(sB[j]); s3B[2 * j + 1] = hi2(sB[j]);
            }
        }

        rqs_step(s3A, zA, ladjA);
        rqs_step(s3B, zB, ladjB);
    }

    float lpA = -0.5f * zA * zA + NEG_HALF_LOG_2PI + ladjA;
    float lpB = -0.5f * zB * zB + NEG_HALF_LOG_2PI + ladjB;
    if (validA) out_logprob[rowA] = lpA;
    if (validB) out_logprob[rowB] = lpB;

    // ---- deterministic block reduction for nll partial ----
    __syncthreads();
    double* sd = reinterpret_cast<double*>(smem);
    sd[tid] = (validA ? (double)lpA : 0.0) + (validB ? (double)lpB : 0.0);
    __syncthreads();
    if (tid < 48) sd[tid] += sd[tid + 48];
    __syncthreads();
    if (tid < 24) sd[tid] += sd[tid + 24];
    __syncthreads();
    if (tid < 12) sd[tid] += sd[tid + 12];
    __syncthreads();
    if (tid < 6) sd[tid] += sd[tid + 6];
    __syncthreads();
    if (tid < 3) sd[tid] += sd[tid + 3];
    __syncthreads();
    if (tid == 0) {
        g_partial[blockIdx.x] = sd[0] + sd[1] + sd[2];
        __threadfence();
        unsigned int ticket = atomicAdd(&g_done, 1u);
        s_islast = (ticket == (unsigned int)(nb - 1)) ? 1 : 0;
    }
    __syncthreads();

    // ---- last CTA reduces all partials ----
    if (s_islast) {
        double s = 0.0;
        for (int i = tid; i < nb; i += TPB) s += g_partial[i];
        sd[tid] = s;
        __syncthreads();
        if (tid < 48) sd[tid] += sd[tid + 48];
        __syncthreads();
        if (tid < 24) sd[tid] += sd[tid + 24];
        __syncthreads();
        if (tid < 12) sd[tid] += sd[tid + 12];
        __syncthreads();
        if (tid < 6) sd[tid] += sd[tid + 6];
        __syncthreads();
        if (tid < 3) sd[tid] += sd[tid + 3];
        __syncthreads();
        if (tid == 0) {
            out_nll[0] = (float)(-(sd[0] + sd[1] + sd[2]) * (double)invB);
            g_done = 0;   // self-reset for next graph replay
        }
    }
}

extern "C" void kernel_launch(void* const* d_in, const int* in_sizes, int n_in,
                              void* d_out, int out_size)
{
    const float* metadata = (const float*)d_in[0];
    const float* prot     = (const float*)d_in[1];
    const float* age      = (const float*)d_in[2];
    const float* maskp    = (const float*)d_in[3];
    const float* eW1 = (const float*)d_in[4];
    const float* eb1 = (const float*)d_in[5];
    const float* eg1 = (const float*)d_in[6];
    const float* eB1 = (const float*)d_in[7];
    const float* eW2 = (const float*)d_in[8];
    const float* eb2 = (const float*)d_in[9];
    const float* eg2 = (const float*)d_in[10];
    const float* eB2 = (const float*)d_in[11];
    const float* eW3 = (const float*)d_in[12];
    const float* eb3 = (const float*)d_in[13];
    const float* fW1 = (const float*)d_in[14];
    const float* fb1 = (const float*)d_in[15];
    const float* fW2 = (const float*)d_in[16];
    const float* fb2 = (const float*)d_in[17];
    const float* fW3 = (const float*)d_in[18];
    const float* fb3 = (const float*)d_in[19];

    const int B = in_sizes[1];
    const int T = in_sizes[15] / 64;

    float* out         = (float*)d_out;
    float* out_latent  = out;
    float* out_logprob = out + (size_t)B * 32;
    float* out_nll     = out + (size_t)B * 33;

    int nb = (B + ROWS - 1) / ROWS;
    size_t shmem = (size_t)SMEM_FLOATS * sizeof(float);
    cudaFuncSetAttribute(fused_kernel, cudaFuncAttributeMaxDynamicSharedMemorySize, (int)shmem);

    fused_kernel<<<nb, TPB, shmem>>>(
        metadata, prot, age, maskp,
        eW1, eb1, eg1, eB1, eW2, eb2, eg2, eB2, eW3, eb3,
        fW1, fb1, fW2, fb2, fW3, fb3,
        out_latent, out_logprob, out_nll, B, T, nb, 1.0f / (float)B);
}

// round 11
// speedup vs baseline: 1.2053x; 1.2053x over previous
#include <cuda_runtime.h>
#include <math.h>

#define TPB 192
#define ROWS 192
#define RQS_BOUND 5.0f
#define NEG_HALF_LOG_2PI (-0.9189385332046727f)

typedef unsigned long long u64;

// ---- shared memory layout (float offsets) ----
// encoder phase
#define OW1   0      // 22x64 = 1408
#define OB1   1408
#define OG1   1472
#define OBB1  1536
#define OW2   1600   // 64x64 = 4096
#define OB2   5696
#define OG2   5760
#define OBB2  5824
#define OW3   5888   // 64x32 = 2048
#define OB3   7936   // 32
// flow phase overlays
#define FW1   0      // 33x64 = 2112
#define FB1   2112   // 64
#define FW2   2176   // 64x64 = 4096
#define FB2   6272   // 64
#define FW3   6336   // 64x32 (padded from 23) = 2048
#define FB3   8384   // 32 (padded)
#define CTXOFF  8416              // 33 * ROWS = 6336
#define WORKOFF (8416 + 33*ROWS)  // 64 * ROWS = 12288
#define SMEM_FLOATS (WORKOFF + 64*ROWS)   // 27040 floats = 105.6 KB

__device__ double g_partial[16384];
__device__ unsigned int g_done;   // zero-init; last CTA resets each launch

// ---- packed f32x2 helpers (sm_103a FFMA2, PTX-only) ----
static __device__ __forceinline__ u64 pack2(float lo, float hi) {
    u64 r; asm("mov.b64 %0, {%1, %2};" : "=l"(r) : "f"(lo), "f"(hi)); return r;
}
static __device__ __forceinline__ float lo2(u64 v) { return __uint_as_float((unsigned)v); }
static __device__ __forceinline__ float hi2(u64 v) { return __uint_as_float((unsigned)(v >> 32)); }
static __device__ __forceinline__ void ffma2(u64& d, u64 a, u64 b) {
    asm("fma.rn.f32x2 %0, %1, %2, %3;" : "=l"(d) : "l"(a), "l"(b), "l"(d));
}

static __device__ __forceinline__ float softplusf(float x) {
    return fmaxf(x, 0.0f) + __logf(1.0f + __expf(-fabsf(x)));
}
static __device__ __forceinline__ float gelu_exact(float x) {
    return x * normcdff(x);
}

// ---- warp-cooperative GEMM: 32 rows x (32*HALVES) cols per warp ----
// thread = (rowgroup of 8 rows, colgroup of 4 cols); all smem addrs unique
// per instruction -> crossbar-efficient (no broadcast waste).
template<int NIN, int HALVES, int WSTRIDE>
static __device__ __forceinline__ void coop_gemm_acc(
    const float* __restrict__ smem, int woff, int boff, int srcoff,
    int rowbase, int colg, u64 (&acc)[8][2 * HALVES])
{
#pragma unroll
    for (int h = 0; h < HALVES; h++) {
        u64 b0 = *reinterpret_cast<const u64*>(&smem[boff + h * 32 + colg]);
        u64 b1 = *reinterpret_cast<const u64*>(&smem[boff + h * 32 + colg + 2]);
#pragma unroll
        for (int r = 0; r < 8; r++) { acc[r][2 * h] = b0; acc[r][2 * h + 1] = b1; }
    }
#pragma unroll 4
    for (int i = 0; i < NIN; i++) {
        const float4 a0 = *reinterpret_cast<const float4*>(&smem[srcoff + i * ROWS + rowbase]);
        const float4 a1 = *reinterpret_cast<const float4*>(&smem[srcoff + i * ROWS + rowbase + 4]);
        u64 w[2 * HALVES];
#pragma unroll
        for (int h = 0; h < HALVES; h++) {
            ulonglong2 wv = *reinterpret_cast<const ulonglong2*>(
                &smem[woff + i * WSTRIDE + h * 32 + colg]);
            w[2 * h] = wv.x; w[2 * h + 1] = wv.y;
        }
        const float av[8] = {a0.x, a0.y, a0.z, a0.w, a1.x, a1.y, a1.z, a1.w};
#pragma unroll
        for (int r = 0; r < 8; r++) {
            u64 ar = pack2(av[r], av[r]);
#pragma unroll
            for (int k = 0; k < 2 * HALVES; k++) ffma2(acc[r][k], ar, w[k]);
        }
    }
}

// store acc tile to column-major smem work region; optional fused ReLU
template<int HALVES, bool RELU>
static __device__ __forceinline__ void coop_store(
    float* __restrict__ smem, int dstoff, int rowbase, int colg,
    const u64 (&acc)[8][2 * HALVES])
{
#pragma unroll
    for (int h = 0; h < HALVES; h++) {
#pragma unroll
        for (int cc = 0; cc < 4; cc++) {
            const int col = h * 32 + colg + cc;
            const int ki = 2 * h + (cc >> 1);
            float e[8];
#pragma unroll
            for (int r = 0; r < 8; r++)
                e[r] = (cc & 1) ? hi2(acc[r][ki]) : lo2(acc[r][ki]);
            if (RELU) {
#pragma unroll
                for (int r = 0; r < 8; r++) e[r] = fmaxf(e[r], 0.0f);
            }
            *reinterpret_cast<float4*>(&smem[dstoff + col * ROWS + rowbase]) =
                make_float4(e[0], e[1], e[2], e[3]);
            *reinterpret_cast<float4*>(&smem[dstoff + col * ROWS + rowbase + 4]) =
                make_float4(e[4], e[5], e[6], e[7]);
        }
    }
}

// per-row LayerNorm + exact GELU over 64 feats in WORK columns (in place)
static __device__ __forceinline__ void ln_gelu_rowpass(
    float* __restrict__ smem, int go, int bo, int tid)
{
    float v[64];
#pragma unroll
    for (int f = 0; f < 64; f++) v[f] = smem[WORKOFF + f * ROWS + tid];
    float mu = 0.0f;
#pragma unroll
    for (int f = 0; f < 64; f++) mu += v[f];
    mu *= (1.0f / 64.0f);
    float var = 0.0f;
#pragma unroll
    for (int f = 0; f < 64; f++) { float c = v[f] - mu; var += c * c; }
    var *= (1.0f / 64.0f);
    float inv = rsqrtf(var + 1e-5f);
#pragma unroll
    for (int f = 0; f < 64; f++) {
        float x = (v[f] - mu) * inv * smem[go + f] + smem[bo + f];
        smem[WORKOFF + f * ROWS + tid] = gelu_exact(x);
    }
}

// rational-quadratic spline step for one row
static __device__ __forceinline__ void rqs_step(const float* s3, float& z, float& ladj)
{
    float w8[8], h8[8];
#pragma unroll
    for (int m = 0; m < 8; m++) { w8[m] = s3[m]; h8[m] = s3[8 + m]; }

    float mw = w8[0], mh = h8[0];
#pragma unroll
    for (int m = 1; m < 8; m++) { mw = fmaxf(mw, w8[m]); mh = fmaxf(mh, h8[m]); }
    float sw = 0.0f, sh = 0.0f;
#pragma unroll
    for (int m = 0; m < 8; m++) {
        w8[m] = __expf(w8[m] - mw); sw += w8[m];
        h8[m] = __expf(h8[m] - mh); sh += h8[m];
    }
    float scw = __fdividef(2.0f * RQS_BOUND, sw);
    float sch = __fdividef(2.0f * RQS_BOUND, sh);

    float xs[9], ys[9], ds[9];
    xs[0] = -RQS_BOUND; ys[0] = -RQS_BOUND;
    float cw = 0.0f, ch = 0.0f;
#pragma unroll
    for (int m = 0; m < 8; m++) {
        cw += w8[m] * scw; xs[m + 1] = -RQS_BOUND + cw;
        ch += h8[m] * sch; ys[m + 1] = -RQS_BOUND + ch;
    }
    ds[0] = 1.0f; ds[8] = 1.0f;
#pragma unroll
    for (int m = 0; m < 7; m++) ds[m + 1] = softplusf(s3[16 + m]);

    bool inside = (z > -RQS_BOUND) && (z < RQS_BOUND);
    float xc = fminf(fmaxf(z, -RQS_BOUND), RQS_BOUND);

    int k = -1;
#pragma unroll
    for (int m = 0; m < 8; m++) k += (xc >= xs[m]) ? 1 : 0;
    k = min(max(k, 0), 7);

    float x0 = xs[0], x1 = xs[1], y0 = ys[0], y1 = ys[1], d0 = ds[0], d1 = ds[1];
#pragma unroll
    for (int m = 1; m < 8; m++) {
        if (k == m) { x0 = xs[m]; x1 = xs[m + 1]; y0 = ys[m]; y1 = ys[m + 1]; d0 = ds[m]; d1 = ds[m + 1]; }
    }

    float wk = x1 - x0, hk = y1 - y0;
    float sk = __fdividef(hk, wk);
    float xi = __fdividef(xc - x0, wk);
    float om = 1.0f - xi;
    float den = sk + (d0 + d1 - 2.0f * sk) * xi * om;
    float yin = y0 + hk * __fdividef(sk * xi * xi + d0 * xi * om, den);
    float ldin = 2.0f * (__logf(sk) - __logf(den))
               + __logf(d1 * xi * xi + 2.0f * sk * xi * om + d0 * om * om);
    if (inside) { z = yin; ladj += ldin; }
}

__global__ __launch_bounds__(TPB, 2)
void fused_kernel(
    const float* __restrict__ metadata, const float* __restrict__ prot,
    const float* __restrict__ age,      const float* __restrict__ maskp,
    const float* __restrict__ eW1, const float* __restrict__ eb1,
    const float* __restrict__ eg1, const float* __restrict__ eB1,
    const float* __restrict__ eW2, const float* __restrict__ eb2,
    const float* __restrict__ eg2, const float* __restrict__ eB2,
    const float* __restrict__ eW3, const float* __restrict__ eb3,
    const float* __restrict__ fW1, const float* __restrict__ fb1,
    const float* __restrict__ fW2, const float* __restrict__ fb2,
    const float* __restrict__ fW3, const float* __restrict__ fb3,
    float* __restrict__ out_latent, float* __restrict__ out_logprob,
    float* __restrict__ out_nll, int B, int T, int nb, float invB)
{
    extern __shared__ __align__(16) float smem[];
    __shared__ int s_islast;
    const int tid = threadIdx.x;
    const int lane = tid & 31;
    const int rowbase = (tid >> 5) * 32 + (lane >> 3) * 8;  // tile rows of this thread
    const int colg = (lane & 7) * 4;                        // tile col group
    const long long row = (long long)blockIdx.x * ROWS + tid;
    const bool valid = (row < (long long)B);
    const long long r = valid ? row : 0;
    const long long blockRow0 = (long long)blockIdx.x * ROWS;

    // ---- stage encoder weights ----
    for (int i = tid; i < 1408; i += TPB) smem[OW1 + i] = eW1[i];
    for (int i = tid; i < 4096; i += TPB) smem[OW2 + i] = eW2[i];
    for (int i = tid; i < 2048; i += TPB) smem[OW3 + i] = eW3[i];
    if (tid < 64) {
        smem[OB1 + tid] = eb1[tid]; smem[OG1 + tid] = eg1[tid]; smem[OBB1 + tid] = eB1[tid];
        smem[OB2 + tid] = eb2[tid]; smem[OG2 + tid] = eg2[tid]; smem[OBB2 + tid] = eB2[tid];
    }
    if (tid < 32) smem[OB3 + tid] = eb3[tid];

    // ---- stage inputs (own row) ----
#pragma unroll
    for (int i = 0; i < 11; i++) {
        smem[WORKOFF + i * ROWS + tid]        = metadata[r * 11 + i];
        smem[WORKOFF + (11 + i) * ROWS + tid] = maskp[r * 11 + i];
    }
    smem[CTXOFF + 32 * ROWS + tid] = prot[r];
    __syncthreads();

    u64 acc[8][4];
    u64 acc1[8][2];

    // ---- GEMM1: 22 -> 64 (cooperative), LN+GELU (per-row) ----
    coop_gemm_acc<22, 2, 64>(smem, OW1, OB1, WORKOFF, rowbase, colg, acc);
    __syncwarp();
    coop_store<2, false>(smem, WORKOFF, rowbase, colg, acc);
    __syncwarp();
    ln_gelu_rowpass(smem, OG1, OBB1, tid);
    __syncwarp();

    // ---- GEMM2: 64 -> 64, LN+GELU ----
    coop_gemm_acc<64, 2, 64>(smem, OW2, OB2, WORKOFF, rowbase, colg, acc);
    __syncwarp();
    coop_store<2, false>(smem, WORKOFF, rowbase, colg, acc);
    __syncwarp();
    ln_gelu_rowpass(smem, OG2, OBB2, tid);
    __syncwarp();

    // ---- GEMM3: 64 -> 32 (latent) -> CTX + gmem ----
    coop_gemm_acc<64, 1, 32>(smem, OW3, OB3, WORKOFF, rowbase, colg, acc1);
    __syncwarp();
    coop_store<1, false>(smem, CTXOFF, rowbase, colg, acc1);
#pragma unroll
    for (int rr = 0; rr < 8; rr++) {
        long long grow = blockRow0 + rowbase + rr;
        if (grow < (long long)B) {
            *reinterpret_cast<float4*>(&out_latent[grow * 32 + colg]) =
                make_float4(lo2(acc1[rr][0]), hi2(acc1[rr][0]),
                            lo2(acc1[rr][1]), hi2(acc1[rr][1]));
        }
    }
    __syncwarp();

    // ---- flow transforms ----
    float z = age[r];
    float ladj = 0.0f;

    for (int t = 0; t < T; t++) {
        __syncthreads();
        const float* w1t = fW1 + (long long)t * 2112;
        const float* w2t = fW2 + (long long)t * 4096;
        const float* w3t = fW3 + (long long)t * 1472;
        for (int i = tid; i < 2112; i += TPB) smem[FW1 + i] = w1t[i];
        for (int i = tid; i < 4096; i += TPB) smem[FW2 + i] = w2t[i];
        for (int i = tid; i < 2048; i += TPB) {
            int rr = i >> 5, cc = i & 31;
            smem[FW3 + i] = (cc < 23) ? w3t[rr * 23 + cc] : 0.0f;
        }
        if (tid < 64) {
            smem[FB1 + tid] = fb1[t * 64 + tid];
            smem[FB2 + tid] = fb2[t * 64 + tid];
        }
        if (tid < 32) smem[FB3 + tid] = (tid < 23) ? fb3[t * 23 + tid] : 0.0f;
        __syncthreads();

        // p1 = relu(ctx @ W1 + b1)
        coop_gemm_acc<33, 2, 64>(smem, FW1, FB1, CTXOFF, rowbase, colg, acc);
        __syncwarp();
        coop_store<2, true>(smem, WORKOFF, rowbase, colg, acc);
        __syncwarp();

        // p2 = relu(p1 @ W2 + b2)
        coop_gemm_acc<64, 2, 64>(smem, FW2, FB2, WORKOFF, rowbase, colg, acc);
        __syncwarp();
        coop_store<2, true>(smem, WORKOFF, rowbase, colg, acc);
        __syncwarp();

        // p3 = p2 @ W3 + b3 (23 cols, padded to 32)
        coop_gemm_acc<64, 1, 32>(smem, FW3, FB3, WORKOFF, rowbase, colg, acc1);
        __syncwarp();
        coop_store<1, false>(smem, WORKOFF, rowbase, colg, acc1);
        __syncwarp();

        // spline per row
        float s3[23];
#pragma unroll
        for (int j = 0; j < 23; j++) s3[j] = smem[WORKOFF + j * ROWS + tid];
        rqs_step(s3, z, ladj);
    }

    float lp = -0.5f * z * z + NEG_HALF_LOG_2PI + ladj;
    if (valid) out_logprob[row] = lp;

    // ---- deterministic block reduction for nll partial ----
    __syncthreads();
    double* sd = reinterpret_cast<double*>(smem);
    sd[tid] = valid ? (double)lp : 0.0;
    __syncthreads();
    if (tid < 96) sd[tid] += sd[tid + 96];
    __syncthreads();
    if (tid < 48) sd[tid] += sd[tid + 48];
    __syncthreads();
    if (tid < 24) sd[tid] += sd[tid + 24];
    __syncthreads();
    if (tid < 12) sd[tid] += sd[tid + 12];
    __syncthreads();
    if (tid < 6) sd[tid] += sd[tid + 6];
    __syncthreads();
    if (tid < 3) sd[tid] += sd[tid + 3];
    __syncthreads();
    if (tid == 0) {
        g_partial[blockIdx.x] = sd[0] + sd[1] + sd[2];
        __threadfence();
        unsigned int ticket = atomicAdd(&g_done, 1u);
        s_islast = (ticket == (unsigned int)(nb - 1)) ? 1 : 0;
    }
    __syncthreads();

    // ---- last CTA reduces all partials ----
    if (s_islast) {
        double s = 0.0;
        for (int i = tid; i < nb; i += TPB) s += g_partial[i];
        sd[tid] = s;
        __syncthreads();
        if (tid < 96) sd[tid] += sd[tid + 96];
        __syncthreads();
        if (tid < 48) sd[tid] += sd[tid + 48];
        __syncthreads();
        if (tid < 24) sd[tid] += sd[tid + 24];
        __syncthreads();
        if (tid < 12) sd[tid] += sd[tid + 12];
        __syncthreads();
        if (tid < 6) sd[tid] += sd[tid + 6];
        __syncthreads();
        if (tid < 3) sd[tid] += sd[tid + 3];
        __syncthreads();
        if (tid == 0) {
            out_nll[0] = (float)(-(sd[0] + sd[1] + sd[2]) * (double)invB);
            g_done = 0;   // self-reset for next graph replay
        }
    }
}

extern "C" void kernel_launch(void* const* d_in, const int* in_sizes, int n_in,
                              void* d_out, int out_size)
{
    const float* metadata = (const float*)d_in[0];
    const float* prot     = (const float*)d_in[1];
    const float* age      = (const float*)d_in[2];
    const float* maskp    = (const float*)d_in[3];
    const float* eW1 = (const float*)d_in[4];
    const float* eb1 = (const float*)d_in[5];
    const float* eg1 = (const float*)d_in[6];
    const float* eB1 = (const float*)d_in[7];
    const float* eW2 = (const float*)d_in[8];
    const float* eb2 = (const float*)d_in[9];
    const float* eg2 = (const float*)d_in[10];
    const float* eB2 = (const float*)d_in[11];
    const float* eW3 = (const float*)d_in[12];
    const float* eb3 = (const float*)d_in[13];
    const float* fW1 = (const float*)d_in[14];
    const float* fb1 = (const float*)d_in[15];
    const float* fW2 = (const float*)d_in[16];
    const float* fb2 = (const float*)d_in[17];
    const float* fW3 = (const float*)d_in[18];
    const float* fb3 = (const float*)d_in[19];

    const int B = in_sizes[1];
    const int T = in_sizes[15] / 64;

    float* out         = (float*)d_out;
    float* out_latent  = out;
    float* out_logprob = out + (size_t)B * 32;
    float* out_nll     = out + (size_t)B * 33;

    int nb = (B + ROWS - 1) / ROWS;
    size_t shmem = (size_t)SMEM_FLOATS * sizeof(float);
    cudaFuncSetAttribute(fused_kernel, cudaFuncAttributeMaxDynamicSharedMemorySize, (int)shmem);

    fused_kernel<<<nb, TPB, shmem>>>(
        metadata, prot, age, maskp,
        eW1, eb1, eg1, eB1, eW2, eb2, eg2, eB2, eW3, eb3,
        fW1, fb1, fW2, fb2, fW3, fb3,
        out_latent, out_logprob, out_nll, B, T, nb, 1.0f / (float)B);
}